// round 5
// baseline (speedup 1.0000x reference)
#include <cuda_runtime.h>
#include <math.h>

#define NN      4096   // nodes
#define INDIM   512
#define QKVD    512    // OUT_DIM * NUM_HEADS
#define NHEAD   8
#define ODIM    64
#define MAXNBR  512

// Scratch (allocation-free rule: __device__ globals)
__device__ float g_Q[NN * QKVD];
__device__ float g_K[NN * QKVD];
__device__ float g_V[NN * QKVD];
__device__ float g_Tv[QKVD];

// ---------------------------------------------------------------------------
// Fused QKV SGEMM: C = h @ W + b  (Q additionally scaled by 0.125)
// BM=128, BN=128, BK=8, 256 threads, 8x8 microtile.
// Grid: x = 12 column tiles (0-3 -> Q, 4-7 -> K, 8-11 -> V), y = 32 row tiles.
// ---------------------------------------------------------------------------
__global__ __launch_bounds__(256) void qkv_gemm(
    const float* __restrict__ Hm,
    const float* __restrict__ Wq, const float* __restrict__ bq,
    const float* __restrict__ Wk, const float* __restrict__ bk,
    const float* __restrict__ Wv, const float* __restrict__ bv)
{
    __shared__ float As[8][128];
    __shared__ float Bs[8][128];

    const int tid  = threadIdx.x;
    const int sel  = blockIdx.x >> 2;          // 0=Q, 1=K, 2=V
    const int n0   = (blockIdx.x & 3) * 128;   // col offset within the 512-wide output
    const int m0   = blockIdx.y * 128;

    const float* W    = (sel == 0) ? Wq : (sel == 1) ? Wk : Wv;
    const float* bias = (sel == 0) ? bq : (sel == 1) ? bk : bv;
    float*       C    = (sel == 0) ? g_Q : (sel == 1) ? g_K : g_V;
    const float scale = (sel == 0) ? 0.125f : 1.0f;  // OUT_DIM^-0.5

    // A-tile load map: one float4 per thread per k-tile
    const int arow = tid >> 1;          // 0..127
    const int acol = (tid & 1) * 4;     // 0 or 4
    // B-tile load map
    const int brow = tid >> 5;          // 0..7
    const int bcol = (tid & 31) * 4;    // 0..124

    const int tx = tid & 15;            // col group
    const int ty = tid >> 4;            // row group

    float acc[8][8];
#pragma unroll
    for (int i = 0; i < 8; i++)
#pragma unroll
        for (int j = 0; j < 8; j++) acc[i][j] = 0.f;

    for (int k0 = 0; k0 < INDIM; k0 += 8) {
        float4 a4 = *(const float4*)(Hm + (size_t)(m0 + arow) * INDIM + k0 + acol);
        As[acol + 0][arow] = a4.x;
        As[acol + 1][arow] = a4.y;
        As[acol + 2][arow] = a4.z;
        As[acol + 3][arow] = a4.w;
        *(float4*)&Bs[brow][bcol] =
            *(const float4*)(W + (size_t)(k0 + brow) * QKVD + n0 + bcol);
        __syncthreads();

#pragma unroll
        for (int kk = 0; kk < 8; kk++) {
            float a[8], b[8];
            *(float4*)&a[0] = *(const float4*)&As[kk][ty * 8];
            *(float4*)&a[4] = *(const float4*)&As[kk][ty * 8 + 4];
            *(float4*)&b[0] = *(const float4*)&Bs[kk][tx * 8];
            *(float4*)&b[4] = *(const float4*)&Bs[kk][tx * 8 + 4];
#pragma unroll
            for (int i = 0; i < 8; i++)
#pragma unroll
                for (int j = 0; j < 8; j++)
                    acc[i][j] = fmaf(a[i], b[j], acc[i][j]);
        }
        __syncthreads();
    }

#pragma unroll
    for (int i = 0; i < 8; i++) {
        const int gm = m0 + ty * 8 + i;
#pragma unroll
        for (int j = 0; j < 8; j += 4) {
            const int gn = n0 + tx * 8 + j;
            float4 bb = *(const float4*)(bias + gn);
            float4 o;
            o.x = (acc[i][j + 0] + bb.x) * scale;
            o.y = (acc[i][j + 1] + bb.y) * scale;
            o.z = (acc[i][j + 2] + bb.z) * scale;
            o.w = (acc[i][j + 3] + bb.w) * scale;
            *(float4*)(C + (size_t)gm * QKVD + gn) = o;
        }
    }
}

// ---------------------------------------------------------------------------
// Tv[c] = sum_m V[m, c]   (zero + partial-sum w/ atomics for parallelism)
// ---------------------------------------------------------------------------
__global__ void zero_tv_kernel() {
    int c = blockIdx.x * 256 + threadIdx.x;
    if (c < QKVD) g_Tv[c] = 0.f;
}

__global__ __launch_bounds__(512) void colsum_v_kernel() {
    const int c  = threadIdx.x;            // 512 threads = all columns
    const int r0 = blockIdx.x * 128;       // 32 blocks x 128 rows
    float s = 0.f;
#pragma unroll 4
    for (int r = r0; r < r0 + 128; r++)
        s += g_V[(size_t)r * QKVD + c];
    atomicAdd(&g_Tv[c], s);
}

// ---------------------------------------------------------------------------
// Edge attention + head-softmax + output.
// One block per row n (256 threads, 8 warps).
// out[h*NN*ODIM + n*ODIM + d] = 0.125*Tv[d*8+h]
//                             + sum_{m in nbr(n)} (w_h(n,m)-0.125) * V[m, d*8+h]
// ---------------------------------------------------------------------------
__global__ __launch_bounds__(256) void attn_kernel(
    const float* __restrict__ A, float* __restrict__ out)
{
    __shared__ float qrow[QKVD];
    __shared__ float acc[8][QKVD];   // per-warp privatized accumulators
    __shared__ int   nbr[MAXNBR];
    __shared__ int   cnt;

    const int n    = blockIdx.x;
    const int tid  = threadIdx.x;
    const int lane = tid & 31;
    const int wid  = tid >> 5;

    if (tid == 0) cnt = 0;
#pragma unroll
    for (int i = tid; i < QKVD; i += 256) qrow[i] = g_Q[(size_t)n * QKVD + i];
#pragma unroll
    for (int i = tid; i < 8 * QKVD; i += 256) (&acc[0][0])[i] = 0.f;
    __syncthreads();

    // Compact this row's nonzeros of A
    const float* Arow = A + (size_t)n * NN;
    for (int m = tid; m < NN; m += 256) {
        if (Arow[m] != 0.0f) {
            int p = atomicAdd(&cnt, 1);
            if (p < MAXNBR) nbr[p] = m;
        }
    }
    __syncthreads();
    const int count = min(cnt, MAXNBR);

    float* myacc = acc[wid];
    for (int i = wid; i < count; i += 8) {
        const int m = nbr[i];
        const float* Krow = g_K + (size_t)m * QKVD;
        const float* Vrow = g_V + (size_t)m * QKVD;

        // Lane l handles columns c = l + 32j; c%8 == l%8 => one head per lane.
        float s = 0.f;
#pragma unroll
        for (int j = 0; j < 16; j++) {
            const int c = lane + 32 * j;
            s = fmaf(qrow[c], Krow[c], s);
        }
        // Sum over lanes sharing the same head (l, l+8, l+16, l+24)
        s += __shfl_xor_sync(0xffffffffu, s, 8);
        s += __shfl_xor_sync(0xffffffffu, s, 16);

        // Softmax over the 8 heads (groups of 8 consecutive lanes hold heads 0..7)
        float mx = s;
        mx = fmaxf(mx, __shfl_xor_sync(0xffffffffu, mx, 1));
        mx = fmaxf(mx, __shfl_xor_sync(0xffffffffu, mx, 2));
        mx = fmaxf(mx, __shfl_xor_sync(0xffffffffu, mx, 4));
        float e = expf(s - mx);
        float sm = e;
        sm += __shfl_xor_sync(0xffffffffu, sm, 1);
        sm += __shfl_xor_sync(0xffffffffu, sm, 2);
        sm += __shfl_xor_sync(0xffffffffu, sm, 4);
        const float w = e / sm - 0.125f;   // subtract masked baseline

        // Accumulate (w - 1/8) * V ; lane's columns all belong to its head.
#pragma unroll
        for (int j = 0; j < 16; j++) {
            const int c = lane + 32 * j;
            myacc[c] = fmaf(w, Vrow[c], myacc[c]);
        }
    }
    __syncthreads();

    // Reduce warp accumulators, add 1/8 * Tv, write to (H,N,D)-flat output.
    for (int t = tid; t < QKVD; t += 256) {
        const int d = t & 63;
        const int h = t >> 6;
        const int c = d * 8 + h;
        float tot = 0.125f * g_Tv[c];
#pragma unroll
        for (int w8 = 0; w8 < 8; w8++) tot += acc[w8][c];
        out[(size_t)h * (NN * ODIM) + (size_t)n * ODIM + d] = tot;
    }
}

// ---------------------------------------------------------------------------
extern "C" void kernel_launch(void* const* d_in, const int* in_sizes, int n_in,
                              void* d_out, int out_size)
{
    const float* A  = (const float*)d_in[0];
    const float* h  = (const float*)d_in[1];
    const float* Wq = (const float*)d_in[2];
    const float* bq = (const float*)d_in[3];
    const float* Wk = (const float*)d_in[4];
    const float* bk = (const float*)d_in[5];
    const float* Wv = (const float*)d_in[6];
    const float* bv = (const float*)d_in[7];
    float* out = (float*)d_out;

    dim3 ggrid(12, NN / 128);   // 3 outputs x 4 col-tiles, 32 row-tiles
    qkv_gemm<<<ggrid, 256>>>(h, Wq, bq, Wk, bk, Wv, bv);
    zero_tv_kernel<<<2, 256>>>();
    colsum_v_kernel<<<32, 512>>>();
    attn_kernel<<<NN, 256>>>(A, out);
}

// round 8
// speedup vs baseline: 1.1224x; 1.1224x over previous
#include <cuda_runtime.h>
#include <mma.h>
#include <math.h>

using namespace nvcuda;

#define NN      4096   // nodes
#define INDIM   512
#define QKVD    512    // OUT_DIM * NUM_HEADS
#define NHEAD   8
#define ODIM    64
#define MAXNBR  512

// Scratch (allocation-free rule: __device__ globals)
__device__ float g_Q[NN * QKVD];
__device__ float g_K[NN * QKVD];
__device__ float g_V[NN * QKVD];
__device__ float g_Tv[QKVD];

// ---------------------------------------------------------------------------
// Fused QKV GEMM on tensor cores (tf32 wmma m16n16k8).
// C = h @ W + b, Q additionally scaled by 0.125.
// Block tile 128x64, BK=32, 256 threads = 8 warps in a 4x2 warp grid,
// each warp owns a 32x32 tile (2x2 wmma fragments).
// Grid: x = 8 col tiles, y = 32 row tiles, z = {Q,K,V}.
// ---------------------------------------------------------------------------
#define BM 128
#define BN 64
#define BK 32
#define LDA 40   // BK + 8 pad (multiple of 8 for wmma ldm)
#define LDB 72   // BN + 8 pad

__global__ __launch_bounds__(256) void qkv_gemm_tc(
    const float* __restrict__ Hm,
    const float* __restrict__ Wq, const float* __restrict__ bq,
    const float* __restrict__ Wk, const float* __restrict__ bk,
    const float* __restrict__ Wv, const float* __restrict__ bv)
{
    __shared__ float smem[8192];                 // 32KB, unioned
    float* As = smem;                            // [BM][LDA] = 5120 floats
    float* Bs = smem + BM * LDA;                 // [BK][LDB] = 2304 floats
    float* Cs = smem;                            // epilogue [BM][BN] = 8192 floats

    const int tid = threadIdx.x;
    const int sel = blockIdx.z;                  // 0=Q, 1=K, 2=V
    const int n0  = blockIdx.x * BN;
    const int m0  = blockIdx.y * BM;

    const float* W    = (sel == 0) ? Wq : (sel == 1) ? Wk : Wv;
    const float* bias = (sel == 0) ? bq : (sel == 1) ? bk : bv;
    float*       C    = (sel == 0) ? g_Q : (sel == 1) ? g_K : g_V;
    const float scale = (sel == 0) ? 0.125f : 1.0f;

    const int wid = tid >> 5;
    const int wr  = wid >> 1;                    // warp row 0..3  (32-row slab)
    const int wc  = wid & 1;                     // warp col 0..1  (32-col slab)

    // A-tile load map: 128x32 floats, 16 per thread (4 float4)
    const int ar = tid >> 1;                     // 0..127
    const int ac = (tid & 1) * 16;               // 0 or 16
    // B-tile load map: 32x64 floats, 8 per thread (2 float4)
    const int br = tid >> 3;                     // 0..31
    const int bc = (tid & 7) * 8;                // 0..56

    wmma::fragment<wmma::accumulator, 16, 16, 8, float> acc[2][2];
#pragma unroll
    for (int i = 0; i < 2; i++)
#pragma unroll
        for (int j = 0; j < 2; j++) wmma::fill_fragment(acc[i][j], 0.0f);

    for (int k0 = 0; k0 < INDIM; k0 += BK) {
        // Load + tf32-round A tile
        const float* ga = Hm + (size_t)(m0 + ar) * INDIM + k0 + ac;
        float* da = As + ar * LDA + ac;
#pragma unroll
        for (int q = 0; q < 4; q++) {
            float4 v = *(const float4*)(ga + 4 * q);
            da[4 * q + 0] = wmma::__float_to_tf32(v.x);
            da[4 * q + 1] = wmma::__float_to_tf32(v.y);
            da[4 * q + 2] = wmma::__float_to_tf32(v.z);
            da[4 * q + 3] = wmma::__float_to_tf32(v.w);
        }
        // Load + tf32-round B tile
        const float* gb = W + (size_t)(k0 + br) * QKVD + n0 + bc;
        float* db = Bs + br * LDB + bc;
#pragma unroll
        for (int q = 0; q < 2; q++) {
            float4 v = *(const float4*)(gb + 4 * q);
            db[4 * q + 0] = wmma::__float_to_tf32(v.x);
            db[4 * q + 1] = wmma::__float_to_tf32(v.y);
            db[4 * q + 2] = wmma::__float_to_tf32(v.z);
            db[4 * q + 3] = wmma::__float_to_tf32(v.w);
        }
        __syncthreads();

#pragma unroll
        for (int kk = 0; kk < BK; kk += 8) {
            wmma::fragment<wmma::matrix_a, 16, 16, 8, wmma::precision::tf32, wmma::row_major> a0, a1;
            wmma::fragment<wmma::matrix_b, 16, 16, 8, wmma::precision::tf32, wmma::row_major> b0, b1;
            wmma::load_matrix_sync(a0, As + (wr * 32 +  0) * LDA + kk, LDA);
            wmma::load_matrix_sync(a1, As + (wr * 32 + 16) * LDA + kk, LDA);
            wmma::load_matrix_sync(b0, Bs + kk * LDB + wc * 32 +  0, LDB);
            wmma::load_matrix_sync(b1, Bs + kk * LDB + wc * 32 + 16, LDB);
            wmma::mma_sync(acc[0][0], a0, b0, acc[0][0]);
            wmma::mma_sync(acc[0][1], a0, b1, acc[0][1]);
            wmma::mma_sync(acc[1][0], a1, b0, acc[1][0]);
            wmma::mma_sync(acc[1][1], a1, b1, acc[1][1]);
        }
        __syncthreads();
    }

    // Epilogue: park fragments in shared (aliases As/Bs, all reads done), then
    // bias+scale and write coalesced float4.
#pragma unroll
    for (int i = 0; i < 2; i++)
#pragma unroll
        for (int j = 0; j < 2; j++)
            wmma::store_matrix_sync(Cs + (wr * 32 + i * 16) * BN + wc * 32 + j * 16,
                                    acc[i][j], BN, wmma::mem_row_major);
    __syncthreads();

#pragma unroll
    for (int e = tid; e < BM * BN / 4; e += 256) {   // 8 iterations
        const int r = e >> 4;
        const int c = (e & 15) * 4;
        float4 v  = *(float4*)&Cs[r * BN + c];
        float4 bb = *(const float4*)(bias + n0 + c);
        float4 o;
        o.x = (v.x + bb.x) * scale;
        o.y = (v.y + bb.y) * scale;
        o.z = (v.z + bb.z) * scale;
        o.w = (v.w + bb.w) * scale;
        *(float4*)(C + (size_t)(m0 + r) * QKVD + n0 + c) = o;
    }
}

// ---------------------------------------------------------------------------
// Tv[c] = sum_m V[m, c]
// ---------------------------------------------------------------------------
__global__ void zero_tv_kernel() {
    int c = blockIdx.x * 256 + threadIdx.x;
    if (c < QKVD) g_Tv[c] = 0.f;
}

__global__ __launch_bounds__(512) void colsum_v_kernel() {
    const int c  = threadIdx.x;            // 512 threads = all columns
    const int r0 = blockIdx.x * 128;       // 32 blocks x 128 rows
    float s = 0.f;
#pragma unroll 4
    for (int r = r0; r < r0 + 128; r++)
        s += g_V[(size_t)r * QKVD + c];
    atomicAdd(&g_Tv[c], s);
}

// ---------------------------------------------------------------------------
// Edge attention + head-softmax + output. One block per row n, 8 warps.
// All accumulation in registers; float4 loads of Q/K/V.
// Lane l, chunk j covers columns c = 4*l + 128*j + e (e = 0..3).
// head(c) = c % 8 = (4*l + e) % 8 -> even lanes own heads 0-3, odd lanes 4-7,
// identical for every chunk j, so softmax weights apply elementwise.
// ---------------------------------------------------------------------------
__global__ __launch_bounds__(256) void attn_kernel(
    const float* __restrict__ A, float* __restrict__ out)
{
    __shared__ int   nbr[MAXNBR];
    __shared__ int   cnt;
    __shared__ float accs[QKVD];

    const int n    = blockIdx.x;
    const int tid  = threadIdx.x;
    const int lane = tid & 31;
    const int wid  = tid >> 5;

    if (tid == 0) cnt = 0;
#pragma unroll
    for (int i = tid; i < QKVD; i += 256) accs[i] = 0.f;

    // Q row into registers (float4 per chunk)
    const float4* Q4 = (const float4*)g_Q + (size_t)n * 128;
    float4 qv[4];
#pragma unroll
    for (int j = 0; j < 4; j++) qv[j] = Q4[lane + 32 * j];

    __syncthreads();

    // Compact this row's adjacency nonzeros
    const float* Arow = A + (size_t)n * NN;
    for (int m = tid; m < NN; m += 256) {
        if (Arow[m] != 0.0f) {
            int p = atomicAdd(&cnt, 1);
            if (p < MAXNBR) nbr[p] = m;
        }
    }
    __syncthreads();
    const int count = min(cnt, MAXNBR);

    float4 vacc[4];
#pragma unroll
    for (int j = 0; j < 4; j++) vacc[j] = make_float4(0.f, 0.f, 0.f, 0.f);

    for (int i = wid; i < count; i += 8) {
        const int m = nbr[i];
        const float4* K4 = (const float4*)g_K + (size_t)m * 128;
        const float4* V4 = (const float4*)g_V + (size_t)m * 128;

        float4 kv[4], vv[4];
#pragma unroll
        for (int j = 0; j < 4; j++) kv[j] = K4[lane + 32 * j];
#pragma unroll
        for (int j = 0; j < 4; j++) vv[j] = V4[lane + 32 * j];

        // Per-element partial dots (this lane's 4 heads)
        float4 s = make_float4(0.f, 0.f, 0.f, 0.f);
#pragma unroll
        for (int j = 0; j < 4; j++) {
            s.x = fmaf(qv[j].x, kv[j].x, s.x);
            s.y = fmaf(qv[j].y, kv[j].y, s.y);
            s.z = fmaf(qv[j].z, kv[j].z, s.z);
            s.w = fmaf(qv[j].w, kv[j].w, s.w);
        }
        // Reduce over the 16 lanes of the same parity (same head set)
#pragma unroll
        for (int off = 2; off < 32; off <<= 1) {
            s.x += __shfl_xor_sync(0xffffffffu, s.x, off);
            s.y += __shfl_xor_sync(0xffffffffu, s.y, off);
            s.z += __shfl_xor_sync(0xffffffffu, s.z, off);
            s.w += __shfl_xor_sync(0xffffffffu, s.w, off);
        }
        // Softmax across the 8 heads: this lane has 4, neighbor parity has 4
        float mymax = fmaxf(fmaxf(s.x, s.y), fmaxf(s.z, s.w));
        float gmax  = fmaxf(mymax, __shfl_xor_sync(0xffffffffu, mymax, 1));
        float4 ex;
        ex.x = __expf(s.x - gmax);
        ex.y = __expf(s.y - gmax);
        ex.z = __expf(s.z - gmax);
        ex.w = __expf(s.w - gmax);
        float mysum = ex.x + ex.y + ex.z + ex.w;
        float tot   = mysum + __shfl_xor_sync(0xffffffffu, mysum, 1);
        const float inv = 1.0f / tot;
        float4 w;
        w.x = ex.x * inv - 0.125f;   // subtract masked baseline 1/H
        w.y = ex.y * inv - 0.125f;
        w.z = ex.z * inv - 0.125f;
        w.w = ex.w * inv - 0.125f;

        // Accumulate (w - 1/8) * V elementwise (head-aligned by construction)
#pragma unroll
        for (int j = 0; j < 4; j++) {
            vacc[j].x = fmaf(w.x, vv[j].x, vacc[j].x);
            vacc[j].y = fmaf(w.y, vv[j].y, vacc[j].y);
            vacc[j].z = fmaf(w.z, vv[j].z, vacc[j].z);
            vacc[j].w = fmaf(w.w, vv[j].w, vacc[j].w);
        }
    }

    // Merge warp accumulators once (shared atomics, conflict-free addresses)
#pragma unroll
    for (int j = 0; j < 4; j++) {
        const int c = 4 * lane + 128 * j;
        atomicAdd(&accs[c + 0], vacc[j].x);
        atomicAdd(&accs[c + 1], vacc[j].y);
        atomicAdd(&accs[c + 2], vacc[j].z);
        atomicAdd(&accs[c + 3], vacc[j].w);
    }
    __syncthreads();

    // out[(h, n, d)] = 1/8 * Tv[d*8+h] + accs[d*8+h]
    for (int t = tid; t < QKVD; t += 256) {
        const int d = t & 63;
        const int h = t >> 6;
        const int c = d * 8 + h;
        out[(size_t)h * (NN * ODIM) + (size_t)n * ODIM + d] =
            0.125f * g_Tv[c] + accs[c];
    }
}

// ---------------------------------------------------------------------------
extern "C" void kernel_launch(void* const* d_in, const int* in_sizes, int n_in,
                              void* d_out, int out_size)
{
    const float* A  = (const float*)d_in[0];
    const float* h  = (const float*)d_in[1];
    const float* Wq = (const float*)d_in[2];
    const float* bq = (const float*)d_in[3];
    const float* Wk = (const float*)d_in[4];
    const float* bk = (const float*)d_in[5];
    const float* Wv = (const float*)d_in[6];
    const float* bv = (const float*)d_in[7];
    float* out = (float*)d_out;

    dim3 ggrid(QKVD / BN, NN / BM, 3);   // 8 x 32 x 3
    qkv_gemm_tc<<<ggrid, 256>>>(h, Wq, bq, Wk, bk, Wv, bv);
    zero_tv_kernel<<<2, 256>>>();
    colsum_v_kernel<<<32, 512>>>();
    attn_kernel<<<NN, 256>>>(A, out);
}

// round 11
// speedup vs baseline: 1.6189x; 1.4424x over previous
#include <cuda_runtime.h>
#include <mma.h>
#include <math.h>
#include <cstdint>

using namespace nvcuda;

#define NN      4096
#define INDIM   512
#define QKVD    512    // OUT_DIM * NUM_HEADS
#define NHEAD   8
#define ODIM    64
#define MAXNBR  512

// Scratch (allocation-free rule: __device__ globals)
__device__ float g_Q [NN * QKVD];
__device__ float g_KV[NN * 2 * QKVD];   // row m: [K(512) | V(512)]
__device__ float g_Tv[QKVD];
__device__ int   g_nbr[NN * MAXNBR];
__device__ int   g_cnt[NN];

// ---------------------------------------------------------------------------
// cp.async helpers
// ---------------------------------------------------------------------------
__device__ __forceinline__ void cpa16(float* dst, const float* src) {
    unsigned int d = (unsigned int)__cvta_generic_to_shared(dst);
    asm volatile("cp.async.cg.shared.global [%0], [%1], 16;" :: "r"(d), "l"(src));
}
__device__ __forceinline__ void cp_commit() {
    asm volatile("cp.async.commit_group;");
}
template<int N> __device__ __forceinline__ void cp_wait() {
    asm volatile("cp.async.wait_group %0;" :: "n"(N));
}

// ---------------------------------------------------------------------------
// Fused QKV GEMM, tf32 wmma, cp.async double-buffered.
// C = h @ W (+ bias via an extra MMA k-step), Q scaled by 0.125 in-register.
// BM=128 BN=128 BK=16; 8 warps, each 64x32 (4x2 fragments).
// Grid: (QKVD/BN=4, NN/BM=32, 3)
// ---------------------------------------------------------------------------
#define BM 128
#define BN 128
#define BK 16
#define LDA 20           // BK + 4 pad
#define LDB 132          // BN + 4 pad
#define STG_F (BM*LDA + BK*LDB)   // floats per stage = 2560 + 2112 = 4672

__global__ __launch_bounds__(256) void qkv_gemm_tc(
    const float* __restrict__ Hm,
    const float* __restrict__ Wq, const float* __restrict__ bq,
    const float* __restrict__ Wk, const float* __restrict__ bk,
    const float* __restrict__ Wv, const float* __restrict__ bv)
{
    __shared__ float smem[2 * STG_F];   // 37.4 KB

    const int tid = threadIdx.x;
    const int sel = blockIdx.z;
    const int n0  = blockIdx.x * BN;
    const int m0  = blockIdx.y * BM;

    const float* W    = (sel == 0) ? Wq : (sel == 1) ? Wk : Wv;
    const float* bias = (sel == 0) ? bq : (sel == 1) ? bk : bv;
    float* C; int ldc;
    if (sel == 0)      { C = g_Q;         ldc = QKVD;     }
    else if (sel == 1) { C = g_KV;        ldc = 2 * QKVD; }
    else               { C = g_KV + QKVD; ldc = 2 * QKVD; }

    const int wid = tid >> 5;
    const int wr  = wid >> 2;    // 0..1  (64-row slab)
    const int wc  = wid & 3;     // 0..3  (32-col slab)

    wmma::fragment<wmma::accumulator, 16, 16, 8, float> acc[4][2];
#pragma unroll
    for (int i = 0; i < 4; i++)
#pragma unroll
        for (int j = 0; j < 2; j++) wmma::fill_fragment(acc[i][j], 0.0f);

    // async stage loader: A 128x16, B 16x128 (512 float4 each, 2/thread)
    auto loadStage = [&](int buf, int k0) {
        float* As = smem + buf * STG_F;
        float* Bs = As + BM * LDA;
#pragma unroll
        for (int q = 0; q < 2; q++) {
            int idx = tid + q * 256;
            int r = idx >> 2, c4 = (idx & 3) * 4;
            cpa16(As + r * LDA + c4, Hm + (size_t)(m0 + r) * INDIM + k0 + c4);
        }
#pragma unroll
        for (int q = 0; q < 2; q++) {
            int idx = tid + q * 256;
            int r = idx >> 5, c4 = (idx & 31) * 4;
            cpa16(Bs + r * LDB + c4, W + (size_t)(k0 + r) * QKVD + n0 + c4);
        }
        cp_commit();
    };

    loadStage(0, 0);
    int buf = 0;
#pragma unroll 1
    for (int it = 0; it < INDIM / BK; ++it) {
        if (it + 1 < INDIM / BK) { loadStage(buf ^ 1, (it + 1) * BK); cp_wait<1>(); }
        else                     { cp_wait<0>(); }
        __syncthreads();

        const float* As = smem + buf * STG_F;
        const float* Bs = As + BM * LDA;
#pragma unroll
        for (int kk = 0; kk < BK; kk += 8) {
            wmma::fragment<wmma::matrix_a, 16, 16, 8, wmma::precision::tf32, wmma::row_major> af[4];
            wmma::fragment<wmma::matrix_b, 16, 16, 8, wmma::precision::tf32, wmma::row_major> bf[2];
#pragma unroll
            for (int i = 0; i < 4; i++)
                wmma::load_matrix_sync(af[i], As + (wr * 64 + i * 16) * LDA + kk, LDA);
#pragma unroll
            for (int j = 0; j < 2; j++)
                wmma::load_matrix_sync(bf[j], Bs + kk * LDB + wc * 32 + j * 16, LDB);
#pragma unroll
            for (int i = 0; i < 4; i++)
#pragma unroll
                for (int j = 0; j < 2; j++)
                    wmma::mma_sync(acc[i][j], af[i], bf[j], acc[i][j]);
        }
        __syncthreads();
        buf ^= 1;
    }

    // Bias as one extra MMA k-step: A chunk = ones column, B chunk row0 = bias.
    {
        float* As = smem;
        float* Bs = smem + BM * LDA;
        for (int idx = tid; idx < BM * 8; idx += 256) {
            int r = idx >> 3, c = idx & 7;
            As[r * LDA + c] = (c == 0) ? 1.0f : 0.0f;
        }
        for (int idx = tid; idx < 8 * BN; idx += 256) {
            int r = idx >> 7, c = idx & 127;
            Bs[r * LDB + c] = (r == 0) ? bias[n0 + c] : 0.0f;
        }
        __syncthreads();
        wmma::fragment<wmma::matrix_a, 16, 16, 8, wmma::precision::tf32, wmma::row_major> af[4];
        wmma::fragment<wmma::matrix_b, 16, 16, 8, wmma::precision::tf32, wmma::row_major> bf[2];
#pragma unroll
        for (int i = 0; i < 4; i++)
            wmma::load_matrix_sync(af[i], As + (wr * 64 + i * 16) * LDA, LDA);
#pragma unroll
        for (int j = 0; j < 2; j++)
            wmma::load_matrix_sync(bf[j], Bs + wc * 32 + j * 16, LDB);
#pragma unroll
        for (int i = 0; i < 4; i++)
#pragma unroll
            for (int j = 0; j < 2; j++)
                wmma::mma_sync(acc[i][j], af[i], bf[j], acc[i][j]);
    }

    if (sel == 0) {   // Q scaling folds into fragment registers
#pragma unroll
        for (int i = 0; i < 4; i++)
#pragma unroll
            for (int j = 0; j < 2; j++)
#pragma unroll
                for (int t = 0; t < acc[i][j].num_elements; t++)
                    acc[i][j].x[t] *= 0.125f;
    }

#pragma unroll
    for (int i = 0; i < 4; i++)
#pragma unroll
        for (int j = 0; j < 2; j++)
            wmma::store_matrix_sync(
                C + (size_t)(m0 + wr * 64 + i * 16) * ldc + n0 + wc * 32 + j * 16,
                acc[i][j], ldc, wmma::mem_row_major);
}

// ---------------------------------------------------------------------------
// Deterministic adjacency compaction: one warp per row, ballot prefix.
// ---------------------------------------------------------------------------
__global__ __launch_bounds__(256) void scan_A(const float* __restrict__ A)
{
    const int lane = threadIdx.x & 31;
    const int wid  = threadIdx.x >> 5;
    const int n    = blockIdx.x * 8 + wid;

    const float4* Arow = (const float4*)(A + (size_t)n * NN);
    int* nb = g_nbr + (size_t)n * MAXNBR;
    const unsigned lmask = (1u << lane) - 1u;
    int cnt = 0;

#pragma unroll 4
    for (int j = 0; j < NN / 128; ++j) {
        float4 v = Arow[lane + 32 * j];
        float vs[4] = {v.x, v.y, v.z, v.w};
#pragma unroll
        for (int e = 0; e < 4; e++) {
            bool nz = (vs[e] != 0.0f);
            unsigned msk = __ballot_sync(0xffffffffu, nz);
            if (nz) {
                int pos = cnt + __popc(msk & lmask);
                if (pos < MAXNBR) nb[pos] = 128 * j + 4 * lane + e;
            }
            cnt += __popc(msk);
        }
    }
    if (lane == 0) g_cnt[n] = min(cnt, MAXNBR);
}

// ---------------------------------------------------------------------------
// Tv[c] = sum_m V[m, c]   (V interleaved in g_KV at +512)
// ---------------------------------------------------------------------------
__global__ void zero_tv_kernel() {
    int c = blockIdx.x * 256 + threadIdx.x;
    if (c < QKVD) g_Tv[c] = 0.f;
}

__global__ __launch_bounds__(512) void colsum_v_kernel() {
    const int c  = threadIdx.x;
    const int r0 = blockIdx.x * 128;
    float s = 0.f;
#pragma unroll 4
    for (int r = r0; r < r0 + 128; r++)
        s += g_KV[(size_t)r * 1024 + 512 + c];
    atomicAdd(&g_Tv[c], s);
}

// ---------------------------------------------------------------------------
// Edge attention. One 128-thread block per row n; pure edge work (A pre-
// compacted). Lane l, chunk j covers columns c = 4l + 128j + e; head(c) =
// (4l+e)%8 is j-invariant, so softmax weights apply elementwise.
// ---------------------------------------------------------------------------
__global__ __launch_bounds__(128) void attn_kernel(float* __restrict__ out)
{
    __shared__ float accs[QKVD];

    const int n    = blockIdx.x;
    const int tid  = threadIdx.x;
    const int lane = tid & 31;
    const int wid  = tid >> 5;

    for (int i = tid; i < QKVD; i += 128) accs[i] = 0.f;

    const float4* Q4 = (const float4*)g_Q + (size_t)n * 128;
    float4 qv[4];
#pragma unroll
    for (int j = 0; j < 4; j++) qv[j] = Q4[lane + 32 * j];

    __syncthreads();
    const int  count = g_cnt[n];
    const int* nb    = g_nbr + (size_t)n * MAXNBR;

    float4 vacc[4];
#pragma unroll
    for (int j = 0; j < 4; j++) vacc[j] = make_float4(0.f, 0.f, 0.f, 0.f);

    for (int i = wid; i < count; i += 4) {
        const int m = nb[i];
        const float4* KV = (const float4*)g_KV + (size_t)m * 256;

        float4 kv[4], vv[4];
#pragma unroll
        for (int j = 0; j < 4; j++) kv[j] = KV[lane + 32 * j];
#pragma unroll
        for (int j = 0; j < 4; j++) vv[j] = KV[128 + lane + 32 * j];  // issue early

        float4 s = make_float4(0.f, 0.f, 0.f, 0.f);
#pragma unroll
        for (int j = 0; j < 4; j++) {
            s.x = fmaf(qv[j].x, kv[j].x, s.x);
            s.y = fmaf(qv[j].y, kv[j].y, s.y);
            s.z = fmaf(qv[j].z, kv[j].z, s.z);
            s.w = fmaf(qv[j].w, kv[j].w, s.w);
        }
#pragma unroll
        for (int off = 2; off < 32; off <<= 1) {
            s.x += __shfl_xor_sync(0xffffffffu, s.x, off);
            s.y += __shfl_xor_sync(0xffffffffu, s.y, off);
            s.z += __shfl_xor_sync(0xffffffffu, s.z, off);
            s.w += __shfl_xor_sync(0xffffffffu, s.w, off);
        }
        float mymax = fmaxf(fmaxf(s.x, s.y), fmaxf(s.z, s.w));
        float gmax  = fmaxf(mymax, __shfl_xor_sync(0xffffffffu, mymax, 1));
        float4 ex;
        ex.x = __expf(s.x - gmax);
        ex.y = __expf(s.y - gmax);
        ex.z = __expf(s.z - gmax);
        ex.w = __expf(s.w - gmax);
        float mysum = ex.x + ex.y + ex.z + ex.w;
        float tot   = mysum + __shfl_xor_sync(0xffffffffu, mysum, 1);
        const float inv = 1.0f / tot;
        float4 w;
        w.x = ex.x * inv - 0.125f;
        w.y = ex.y * inv - 0.125f;
        w.z = ex.z * inv - 0.125f;
        w.w = ex.w * inv - 0.125f;

#pragma unroll
        for (int j = 0; j < 4; j++) {
            vacc[j].x = fmaf(w.x, vv[j].x, vacc[j].x);
            vacc[j].y = fmaf(w.y, vv[j].y, vacc[j].y);
            vacc[j].z = fmaf(w.z, vv[j].z, vacc[j].z);
            vacc[j].w = fmaf(w.w, vv[j].w, vacc[j].w);
        }
    }

#pragma unroll
    for (int j = 0; j < 4; j++) {
        const int c = 4 * lane + 128 * j;
        atomicAdd(&accs[c + 0], vacc[j].x);
        atomicAdd(&accs[c + 1], vacc[j].y);
        atomicAdd(&accs[c + 2], vacc[j].z);
        atomicAdd(&accs[c + 3], vacc[j].w);
    }
    __syncthreads();

    for (int t = tid; t < QKVD; t += 128) {
        const int d = t & 63;
        const int h = t >> 6;
        const int c = d * 8 + h;
        out[(size_t)h * (NN * ODIM) + (size_t)n * ODIM + d] =
            0.125f * g_Tv[c] + accs[c];
    }
}

// ---------------------------------------------------------------------------
extern "C" void kernel_launch(void* const* d_in, const int* in_sizes, int n_in,
                              void* d_out, int out_size)
{
    const float* A  = (const float*)d_in[0];
    const float* h  = (const float*)d_in[1];
    const float* Wq = (const float*)d_in[2];
    const float* bq = (const float*)d_in[3];
    const float* Wk = (const float*)d_in[4];
    const float* bk = (const float*)d_in[5];
    const float* Wv = (const float*)d_in[6];
    const float* bv = (const float*)d_in[7];
    float* out = (float*)d_out;

    scan_A<<<NN / 8, 256>>>(A);
    zero_tv_kernel<<<2, 256>>>();
    dim3 ggrid(QKVD / BN, NN / BM, 3);   // 4 x 32 x 3
    qkv_gemm_tc<<<ggrid, 256>>>(h, Wq, bq, Wk, bk, Wv, bv);
    colsum_v_kernel<<<32, 512>>>();
    attn_kernel<<<NN, 128>>>(out);
}